// round 2
// baseline (speedup 1.0000x reference)
#include <cuda_runtime.h>
#include <math.h>

typedef unsigned long long U64;

// ---------------- device scratch (no allocs allowed) ----------------
__device__ float g_cv[4 * 288 * 512];   // (B,T,V) rolling CV
__device__ float g_imp[4 * 288];        // (B,T) summed event impact
__device__ float g_cw[4][5];            // softmax(sigmoid(logits)) / k_i

// ---------------- packed f32x2 helpers (sm_103a) ----------------
static __device__ __forceinline__ U64 pack2(float x) {
    unsigned int u = __float_as_uint(x);
    U64 r;
    asm("mov.b64 %0, {%1, %2};" : "=l"(r) : "r"(u), "r"(u));
    return r;
}
static __device__ __forceinline__ U64 fma2(U64 a, U64 b, U64 c) {
    U64 d;
    asm("fma.rn.f32x2 %0, %1, %2, %3;" : "=l"(d) : "l"(a), "l"(b), "l"(c));
    return d;
}
static __device__ __forceinline__ U64 add2(U64 a, U64 b) {
    U64 d;
    asm("add.rn.f32x2 %0, %1, %2;" : "=l"(d) : "l"(a), "l"(b));
    return d;
}
static __device__ __forceinline__ U64 mul2(U64 a, U64 b) {
    U64 d;
    asm("mul.rn.f32x2 %0, %1, %2;" : "=l"(d) : "l"(a), "l"(b));
    return d;
}

// ---------------- prep: MoE gate MLP + event impact ----------------
__global__ void prep_kernel(const float* __restrict__ events,
                            const float* __restrict__ ef,
                            const float* __restrict__ w1,
                            const float* __restrict__ b1,
                            const float* __restrict__ w2,
                            const float* __restrict__ b2) {
    int tid = threadIdx.x;
    if (tid < 4) {
        int b = tid;
        float h[32];
        #pragma unroll
        for (int j = 0; j < 32; j++) {
            float a = b1[j];
            #pragma unroll
            for (int i = 0; i < 8; i++) a += ef[b * 8 + i] * w1[i * 32 + j];
            h[j] = fmaxf(a, 0.f);
        }
        float lg[5];
        #pragma unroll
        for (int j = 0; j < 5; j++) {
            float a = b2[j];
            #pragma unroll
            for (int i = 0; i < 32; i++) a += h[i] * w2[i * 5 + j];
            lg[j] = 1.f / (1.f + expf(-a));
        }
        float mx = lg[0];
        #pragma unroll
        for (int j = 1; j < 5; j++) mx = fmaxf(mx, lg[j]);
        float e[5], s = 0.f;
        #pragma unroll
        for (int j = 0; j < 5; j++) { e[j] = expf(lg[j] - mx); s += e[j]; }
        const float K[5] = {3.f, 6.f, 12.f, 24.f, 48.f};
        #pragma unroll
        for (int j = 0; j < 5; j++) g_cw[b][j] = e[j] / (s * K[j]);
    } else if (tid >= 8 && tid < 12) {
        int b = tid - 8;
        float r0 = expf(-1.f / 300.f), r1 = expf(-1.f / 600.f), r2 = expf(-1.f / 180.f);
        float y0 = 0.f, y1 = 0.f, y2 = 0.f;
        for (int t = 287; t >= 0; t--) {
            const float* e = events + (b * 288 + t) * 3;
            y0 = e[0] + r0 * y0;
            y1 = e[1] + r1 * y1;
            y2 = e[2] + r2 * y2;
            g_imp[b * 288 + t] = 0.3f * y0 + 0.5f * y1 + 0.2f * y2;
        }
    }
}

// ---------------- rolling CV over WINDOW=60 ----------------
__global__ void cv_kernel(const float* __restrict__ flow) {
    int b = blockIdx.x;
    int v = threadIdx.x;
    const float* f = flow + (size_t)b * 288 * 512 + v;
    float s = 0.f, s2 = 0.f;
    for (int t = 0; t < 288; t++) {
        float a = f[(size_t)t * 512];
        s += a; s2 += a * a;
        if (t >= 60) {
            float o = f[(size_t)(t - 60) * 512];
            s -= o; s2 -= o * o;
        }
        float cv = 0.f;
        if (t >= 59) {
            float mean = s * (1.f / 60.f);
            float var = (s2 - 60.f * mean * mean) * (1.f / 59.f);
            float sd = sqrtf(fmaxf(var, 0.f));
            cv = sd / (mean + 1e-6f);
        }
        g_cv[((size_t)b * 288 + t) * 512 + v] = cv;
    }
}

// ---------------- main fused kernel ----------------
// block: (b, 16 t, 64 v) -> 512 threads, one v-pair each, 32 f32x2 accumulators
__global__ void __launch_bounds__(512, 1)
main_kernel(const float* __restrict__ x,
            const float* __restrict__ fusion_w,
            const float* __restrict__ fusion_b,
            float* __restrict__ out) {
    __shared__ __align__(16) U64 s_w[32][32][2];  // [c][o][{w1,w2}] broadcast-packed, 16KB
    __shared__ U64 s_xs[64][32];                  // t-slab -> in-place exclusive prefix, 16KB
    __shared__ U64 s_seg[8][32];                  // per-segment totals, 2KB

    const int tid = threadIdx.x;
    const int b = blockIdx.z;
    const int t0 = blockIdx.y * 16;
    const int v0 = blockIdx.x * 64;

    // pre-pack weights: W1[o][c]=fusion_w[o*64+c], W2[o][c]=fusion_w[o*64+32+c]
    for (int idx = tid; idx < 2048; idx += 512) {
        int c = idx >> 6, r = idx & 63, o = r >> 1, m = r & 1;
        s_w[c][o][m] = pack2(fusion_w[o * 64 + m * 32 + c]);
    }

    U64 acc[32];
    #pragma unroll
    for (int o = 0; o < 32; o++) acc[o] = pack2(__ldg(fusion_b + o));

    U64 cwp[5], cwn[5];
    #pragma unroll
    for (int i = 0; i < 5; i++) {
        float w = g_cw[b][i];
        cwp[i] = pack2(w);
        cwn[i] = pack2(-w);
    }

    const int col = tid & 31;        // v-pair index
    const int tIdx = tid >> 5;       // 0..15
    const int L = 24 + tIdx;         // slab row of output t
    const U64 negone = pack2(-1.f);

    const int pcol = tid & 31, pseg = tid >> 5;  // prefix-phase mapping (tid<256)

    for (int c = 0; c < 32; c++) {
        __syncthreads();  // protect s_xs reads of previous channel
        const float* xc = x + ((size_t)(b * 32 + c) * 288) * 512 + v0;
        // load t-slab [t0-24, t0+40) x 64 v (zeros outside time range)
        #pragma unroll
        for (int k = 0; k < 4; k++) {
            int idx = tid + k * 512;
            int row = idx >> 5, cc = idx & 31;
            int gt = t0 - 24 + row;
            U64 val = 0ull;
            if (gt >= 0 && gt < 288) val = *(const U64*)(xc + (size_t)gt * 512 + cc * 2);
            s_xs[row][cc] = val;
        }
        __syncthreads();
        // segmented in-place exclusive prefix over t (8 segments of 8)
        if (tid < 256) {
            U64 run = 0ull;
            int base = pseg * 8;
            #pragma unroll
            for (int i = 0; i < 8; i++) {
                U64 tmp = s_xs[base + i][pcol];
                s_xs[base + i][pcol] = run;
                run = add2(run, tmp);
            }
            s_seg[pseg][pcol] = run;
        }
        __syncthreads();
        if (tid < 256 && pseg >= 1) {
            U64 off = s_seg[0][pcol];
            for (int s = 1; s < pseg; s++) off = add2(off, s_seg[s][pcol]);
            int base = pseg * 8;
            #pragma unroll
            for (int i = 0; i < 8; i++)
                s_xs[base + i][pcol] = add2(s_xs[base + i][pcol], off);
        }
        __syncthreads();

        // x value and 5 nested avg-pool windows from the prefix
        U64 x2 = fma2(negone, s_xs[L][col], s_xs[L + 1][col]);
        U64 cb = mul2(cwp[0], s_xs[L + 2][col]);
        cb = fma2(cwn[0], s_xs[L - 1][col], cb);
        cb = fma2(cwp[1], s_xs[L + 3][col], cb);
        cb = fma2(cwn[1], s_xs[L - 3][col], cb);
        cb = fma2(cwp[2], s_xs[L + 6][col], cb);
        cb = fma2(cwn[2], s_xs[L - 6][col], cb);
        cb = fma2(cwp[3], s_xs[L + 12][col], cb);
        cb = fma2(cwn[3], s_xs[L - 12][col], cb);
        cb = fma2(cwp[4], s_xs[L + 24][col], cb);
        cb = fma2(cwn[4], s_xs[L - 24][col], cb);

        #pragma unroll
        for (int o = 0; o < 32; o++) {
            ulonglong2 w = *(const ulonglong2*)&s_w[c][o][0];  // LDS.128 broadcast
            acc[o] = fma2(w.x, x2, acc[o]);
            acc[o] = fma2(w.y, cb, acc[o]);
        }
    }

    // epilogue: out = (fused + x) * (1 + cv) + impact
    const int t = t0 + tIdx;
    const size_t pbase = ((size_t)(b * 32) * 288 + t) * 512 + v0 + col * 2;
    U64 cvu = *(const U64*)(g_cv + ((size_t)b * 288 + t) * 512 + v0 + col * 2);
    U64 m2 = add2(pack2(1.f), cvu);
    U64 imp2 = pack2(g_imp[b * 288 + t]);
    #pragma unroll
    for (int o = 0; o < 32; o++) {
        U64 xo = *(const U64*)(x + pbase + (size_t)o * 288 * 512);
        U64 r = add2(acc[o], xo);
        r = fma2(r, m2, imp2);
        *(U64*)(out + pbase + (size_t)o * 288 * 512) = r;
    }
}

// ---------------- launch ----------------
extern "C" void kernel_launch(void* const* d_in, const int* in_sizes, int n_in,
                              void* d_out, int out_size) {
    const float* flow   = (const float*)d_in[0];
    const float* events = (const float*)d_in[1];
    const float* x      = (const float*)d_in[2];
    const float* ef     = (const float*)d_in[3];
    const float* w1     = (const float*)d_in[4];
    const float* b1     = (const float*)d_in[5];
    const float* w2     = (const float*)d_in[6];
    const float* b2     = (const float*)d_in[7];
    const float* fw     = (const float*)d_in[8];
    const float* fb     = (const float*)d_in[9];
    float* out = (float*)d_out;

    prep_kernel<<<1, 32>>>(events, ef, w1, b1, w2, b2);
    cv_kernel<<<4, 512>>>(flow);
    dim3 grid(8, 18, 4);  // (V/64, T/16, B)
    main_kernel<<<grid, 512>>>(x, fw, fb, out);
}

// round 3
// speedup vs baseline: 1.8874x; 1.8874x over previous
#include <cuda_runtime.h>
#include <math.h>

typedef unsigned long long U64;

// ---------------- device scratch ----------------
__device__ float g_cv[4 * 288 * 512];   // (B,T,V) rolling CV
__device__ float g_imp[4 * 288];        // (B,T) summed event impact
__device__ float g_cw[4][5];            // softmax(sigmoid(logits)) / k_i

// ---------------- packed f32x2 helpers (sm_103a) ----------------
static __device__ __forceinline__ U64 pack2(float x) {
    unsigned int u = __float_as_uint(x);
    U64 r;
    asm("mov.b64 %0, {%1, %2};" : "=l"(r) : "r"(u), "r"(u));
    return r;
}
static __device__ __forceinline__ U64 fma2(U64 a, U64 b, U64 c) {
    U64 d;
    asm("fma.rn.f32x2 %0, %1, %2, %3;" : "=l"(d) : "l"(a), "l"(b), "l"(c));
    return d;
}
static __device__ __forceinline__ U64 add2(U64 a, U64 b) {
    U64 d;
    asm("add.rn.f32x2 %0, %1, %2;" : "=l"(d) : "l"(a), "l"(b));
    return d;
}
static __device__ __forceinline__ U64 mul2(U64 a, U64 b) {
    U64 d;
    asm("mul.rn.f32x2 %0, %1, %2;" : "=l"(d) : "l"(a), "l"(b));
    return d;
}

// ---------------- prep: cv (blocks 0..47) + impact (48..51) + gate (52) ----------------
__global__ void prep_all(const float* __restrict__ flow,
                         const float* __restrict__ events,
                         const float* __restrict__ ef,
                         const float* __restrict__ w1,
                         const float* __restrict__ b1,
                         const float* __restrict__ w2,
                         const float* __restrict__ b2) {
    const int blk = blockIdx.x;
    const int tid = threadIdx.x;

    if (blk < 48) {
        // rolling CV, t-chunk of 24 with up-to-59 halo
        const int b = blk / 12;
        const int c0 = (blk % 12) * 24;
        const int v = tid;
        const float* f = flow + (size_t)b * 288 * 512 + v;
        int tstart = c0 - 59; if (tstart < 0) tstart = 0;
        float s = 0.f, s2 = 0.f;
        for (int t = tstart; t < c0 + 24; t++) {
            float a = f[(size_t)t * 512];
            s += a; s2 += a * a;
            int to = t - 60;
            if (to >= tstart) {
                float o = f[(size_t)to * 512];
                s -= o; s2 -= o * o;
            }
            if (t >= c0) {
                float cv = 0.f;
                if (t >= 59) {
                    float mean = s * (1.f / 60.f);
                    float var = (s2 - 60.f * mean * mean) * (1.f / 59.f);
                    float sd = sqrtf(fmaxf(var, 0.f));
                    cv = sd / (mean + 1e-6f);
                }
                g_cv[((size_t)b * 288 + t) * 512 + v] = cv;
            }
        }
    } else if (blk < 52) {
        // event impact: each thread computes its own suffix sum directly
        const int b = blk - 48;
        const int t = tid;
        if (t < 288) {
            const float dec[3] = {300.f, 600.f, 180.f};
            const float al[3]  = {0.3f, 0.5f, 0.2f};
            float tot = 0.f;
            #pragma unroll
            for (int e = 0; e < 3; e++) {
                float r = expf(-1.f / dec[e]);
                float w = al[e], a = 0.f;
                for (int s = t; s < 288; s++) {
                    a = fmaf(events[((size_t)b * 288 + s) * 3 + e], w, a);
                    w *= r;
                }
                tot += a;
            }
            g_imp[b * 288 + t] = tot;
        }
    } else {
        // MoE gate MLP
        if (tid < 4) {
            int b = tid;
            float h[32];
            #pragma unroll
            for (int j = 0; j < 32; j++) {
                float a = b1[j];
                #pragma unroll
                for (int i = 0; i < 8; i++) a += ef[b * 8 + i] * w1[i * 32 + j];
                h[j] = fmaxf(a, 0.f);
            }
            float lg[5];
            #pragma unroll
            for (int j = 0; j < 5; j++) {
                float a = b2[j];
                #pragma unroll
                for (int i = 0; i < 32; i++) a += h[i] * w2[i * 5 + j];
                lg[j] = 1.f / (1.f + expf(-a));
            }
            float mx = lg[0];
            #pragma unroll
            for (int j = 1; j < 5; j++) mx = fmaxf(mx, lg[j]);
            float e[5], s = 0.f;
            #pragma unroll
            for (int j = 0; j < 5; j++) { e[j] = expf(lg[j] - mx); s += e[j]; }
            const float K[5] = {3.f, 6.f, 12.f, 24.f, 48.f};
            #pragma unroll
            for (int j = 0; j < 5; j++) g_cw[b][j] = e[j] / (s * K[j]);
        }
    }
}

// ---------------- main fused kernel ----------------
// block: (b, 16 t, 64 v) = 512 threads, one v-pair each, 32 f32x2 accumulators.
// Residual x folded into W1 (identity added) -> no epilogue x re-read.
// Slab loads for channel c+1 prefetched into registers during channel c's work.
__global__ void __launch_bounds__(512, 1)
main_kernel(const float* __restrict__ x,
            const float* __restrict__ fusion_w,
            const float* __restrict__ fusion_b,
            float* __restrict__ out) {
    __shared__ __align__(16) U64 s_w[32][64];   // [c][o*2+m], broadcast-packed, 16KB
    __shared__ U64 s_xs[64][32];                // t-slab -> in-place exclusive prefix
    __shared__ U64 s_seg[8][32];

    const int tid = threadIdx.x;
    const int b = blockIdx.z;
    const int t0 = blockIdx.y * 16;
    const int v0 = blockIdx.x * 64;

    // pre-pack weights (+ identity on W1 diagonal for the residual)
    for (int idx = tid; idx < 2048; idx += 512) {
        int c = idx >> 6, r = idx & 63, o = r >> 1, m = r & 1;
        float w = fusion_w[o * 64 + m * 32 + c];
        if (m == 0 && o == c) w += 1.f;
        s_w[c][r] = pack2(w);
    }

    U64 acc[32];
    #pragma unroll
    for (int o = 0; o < 32; o++) acc[o] = pack2(__ldg(fusion_b + o));

    U64 cw[5];
    #pragma unroll
    for (int i = 0; i < 5; i++) cw[i] = pack2(g_cw[b][i]);

    const int col = tid & 31;      // v-pair
    const int tIdx = tid >> 5;     // 0..15
    const int L = 24 + tIdx;
    const U64 neg1 = pack2(-1.f);
    const size_t CH = (size_t)288 * 512;

    // prefetch pointers: thread loads rows {tIdx, tIdx+16, tIdx+32, tIdx+48}
    const float* pbase = x + (size_t)b * 32 * CH + v0 + col * 2;
    const float* pk[4];
    bool vld[4];
    U64 pre[4];
    #pragma unroll
    for (int k = 0; k < 4; k++) {
        int gt = t0 - 24 + tIdx + 16 * k;
        vld[k] = (gt >= 0) && (gt < 288);
        pk[k] = pbase + (size_t)(vld[k] ? gt : 0) * 512;
        pre[k] = vld[k] ? *(const U64*)pk[k] : 0ull;
    }

    for (int c = 0; c < 32; c++) {
        __syncthreads();  // previous channel's readers done
        #pragma unroll
        for (int k = 0; k < 4; k++) s_xs[tIdx + 16 * k][col] = pre[k];
        // prefetch next channel (overlaps scan + fma below)
        if (c < 31) {
            #pragma unroll
            for (int k = 0; k < 4; k++) {
                pk[k] += CH;
                pre[k] = vld[k] ? *(const U64*)pk[k] : 0ull;
            }
        }
        __syncthreads();
        // segmented in-place exclusive prefix over t (8 segments of 8)
        if (tid < 256) {
            int seg = tid >> 5, cl = tid & 31, base = seg * 8;
            U64 run = 0ull;
            #pragma unroll
            for (int i = 0; i < 8; i++) {
                U64 tmp = s_xs[base + i][cl];
                s_xs[base + i][cl] = run;
                run = add2(run, tmp);
            }
            s_seg[seg][cl] = run;
        }
        __syncthreads();
        if (tid < 256) {
            int seg = tid >> 5, cl = tid & 31;
            if (seg >= 1) {
                U64 off = s_seg[0][cl];
                for (int s = 1; s < seg; s++) off = add2(off, s_seg[s][cl]);
                int base = seg * 8;
                #pragma unroll
                for (int i = 0; i < 8; i++)
                    s_xs[base + i][cl] = add2(s_xs[base + i][cl], off);
            }
        }
        __syncthreads();

        // x value and the 5 nested avg-pool window sums from the prefix
        U64 x2 = fma2(neg1, s_xs[L][col],      s_xs[L + 1][col]);
        U64 d0 = fma2(neg1, s_xs[L - 1][col],  s_xs[L + 2][col]);
        U64 d1 = fma2(neg1, s_xs[L - 3][col],  s_xs[L + 3][col]);
        U64 d2 = fma2(neg1, s_xs[L - 6][col],  s_xs[L + 6][col]);
        U64 d3 = fma2(neg1, s_xs[L - 12][col], s_xs[L + 12][col]);
        U64 d4 = fma2(neg1, s_xs[L - 24][col], s_xs[L + 24][col]);
        U64 cb = mul2(cw[0], d0);
        cb = fma2(cw[1], d1, cb);
        cb = fma2(cw[2], d2, cb);
        cb = fma2(cw[3], d3, cb);
        cb = fma2(cw[4], d4, cb);

        #pragma unroll
        for (int o = 0; o < 32; o++) {
            ulonglong2 w = *(const ulonglong2*)&s_w[c][o * 2];  // LDS.128 broadcast
            acc[o] = fma2(w.x, x2, acc[o]);
            acc[o] = fma2(w.y, cb, acc[o]);
        }
    }

    // epilogue: out = (W+I)x-proj * (1+cv) + impact
    const int t = t0 + tIdx;
    U64 cvu = *(const U64*)(g_cv + ((size_t)b * 288 + t) * 512 + v0 + col * 2);
    U64 m2 = add2(pack2(1.f), cvu);
    U64 imp2 = pack2(g_imp[b * 288 + t]);
    float* po = out + ((size_t)b * 32 * CH) + (size_t)t * 512 + v0 + col * 2;
    #pragma unroll
    for (int o = 0; o < 32; o++) {
        *(U64*)(po + (size_t)o * CH) = fma2(acc[o], m2, imp2);
    }
}

// ---------------- launch ----------------
extern "C" void kernel_launch(void* const* d_in, const int* in_sizes, int n_in,
                              void* d_out, int out_size) {
    const float* flow   = (const float*)d_in[0];
    const float* events = (const float*)d_in[1];
    const float* x      = (const float*)d_in[2];
    const float* ef     = (const float*)d_in[3];
    const float* w1     = (const float*)d_in[4];
    const float* b1     = (const float*)d_in[5];
    const float* w2     = (const float*)d_in[6];
    const float* b2     = (const float*)d_in[7];
    const float* fw     = (const float*)d_in[8];
    const float* fb     = (const float*)d_in[9];
    float* out = (float*)d_out;

    prep_all<<<53, 512>>>(flow, events, ef, w1, b1, w2, b2);
    dim3 grid(8, 18, 4);  // (V/64, T/16, B)
    main_kernel<<<grid, 512>>>(x, fw, fb, out);
}

// round 4
// speedup vs baseline: 2.3112x; 1.2246x over previous
#include <cuda_runtime.h>
#include <math.h>

typedef unsigned long long U64;

// ---------------- device scratch ----------------
__device__ float g_cv[4 * 288 * 512];    // (B,T,V) rolling CV
__device__ float g_imp[4 * 288];         // (B,T) summed event impact
__device__ float g_cw[4][5];             // softmax(sigmoid(logits)) / k_i
__device__ ulonglong2 g_wd[1024];        // packed weights [c][o] = {dup(w1+I), dup(w2)}
__device__ U64 g_bd[32];                 // packed dup bias

__constant__ ulonglong2 c_wd[1024];
__constant__ U64 c_bd[32];

// ---------------- packed f32x2 helpers (sm_103a) ----------------
static __device__ __forceinline__ U64 pack2(float x) {
    unsigned int u = __float_as_uint(x);
    U64 r;
    asm("mov.b64 %0, {%1, %2};" : "=l"(r) : "r"(u), "r"(u));
    return r;
}
static __device__ __forceinline__ U64 fma2(U64 a, U64 b, U64 c) {
    U64 d;
    asm("fma.rn.f32x2 %0, %1, %2, %3;" : "=l"(d) : "l"(a), "l"(b), "l"(c));
    return d;
}
static __device__ __forceinline__ U64 add2(U64 a, U64 b) {
    U64 d;
    asm("add.rn.f32x2 %0, %1, %2;" : "=l"(d) : "l"(a), "l"(b));
    return d;
}
static __device__ __forceinline__ U64 mul2(U64 a, U64 b) {
    U64 d;
    asm("mul.rn.f32x2 %0, %1, %2;" : "=l"(d) : "l"(a), "l"(b));
    return d;
}

// ---------------- prep: cv (0..47) + impact (48..51) + gate (52) + weights (53) ----------------
__global__ void prep_all(const float* __restrict__ flow,
                         const float* __restrict__ events,
                         const float* __restrict__ ef,
                         const float* __restrict__ w1,
                         const float* __restrict__ b1,
                         const float* __restrict__ w2,
                         const float* __restrict__ b2,
                         const float* __restrict__ fusion_w,
                         const float* __restrict__ fusion_b) {
    const int blk = blockIdx.x;
    const int tid = threadIdx.x;

    if (blk < 48) {
        // rolling CV, t-chunk of 24 with up-to-59 halo
        const int b = blk / 12;
        const int c0 = (blk % 12) * 24;
        const int v = tid;
        const float* f = flow + (size_t)b * 288 * 512 + v;
        int tstart = c0 - 59; if (tstart < 0) tstart = 0;
        float s = 0.f, s2 = 0.f;
        for (int t = tstart; t < c0 + 24; t++) {
            float a = f[(size_t)t * 512];
            s += a; s2 += a * a;
            int to = t - 60;
            if (to >= tstart) {
                float o = f[(size_t)to * 512];
                s -= o; s2 -= o * o;
            }
            if (t >= c0) {
                float cv = 0.f;
                if (t >= 59) {
                    float mean = s * (1.f / 60.f);
                    float var = (s2 - 60.f * mean * mean) * (1.f / 59.f);
                    float sd = sqrtf(fmaxf(var, 0.f));
                    cv = sd / (mean + 1e-6f);
                }
                g_cv[((size_t)b * 288 + t) * 512 + v] = cv;
            }
        }
    } else if (blk < 52) {
        // event impact: per-thread suffix sum
        const int b = blk - 48;
        const int t = tid;
        if (t < 288) {
            const float dec[3] = {300.f, 600.f, 180.f};
            const float al[3]  = {0.3f, 0.5f, 0.2f};
            float tot = 0.f;
            #pragma unroll
            for (int e = 0; e < 3; e++) {
                float r = expf(-1.f / dec[e]);
                float w = al[e], a = 0.f;
                for (int s = t; s < 288; s++) {
                    a = fmaf(events[((size_t)b * 288 + s) * 3 + e], w, a);
                    w *= r;
                }
                tot += a;
            }
            g_imp[b * 288 + t] = tot;
        }
    } else if (blk == 52) {
        // MoE gate MLP
        if (tid < 4) {
            int b = tid;
            float h[32];
            #pragma unroll
            for (int j = 0; j < 32; j++) {
                float a = b1[j];
                #pragma unroll
                for (int i = 0; i < 8; i++) a += ef[b * 8 + i] * w1[i * 32 + j];
                h[j] = fmaxf(a, 0.f);
            }
            float lg[5];
            #pragma unroll
            for (int j = 0; j < 5; j++) {
                float a = b2[j];
                #pragma unroll
                for (int i = 0; i < 32; i++) a += h[i] * w2[i * 5 + j];
                lg[j] = 1.f / (1.f + expf(-a));
            }
            float mx = lg[0];
            #pragma unroll
            for (int j = 1; j < 5; j++) mx = fmaxf(mx, lg[j]);
            float e[5], s = 0.f;
            #pragma unroll
            for (int j = 0; j < 5; j++) { e[j] = expf(lg[j] - mx); s += e[j]; }
            const float K[5] = {3.f, 6.f, 12.f, 24.f, 48.f};
            #pragma unroll
            for (int j = 0; j < 5; j++) g_cw[b][j] = e[j] / (s * K[j]);
        }
    } else {
        // pack weights into dup-f32x2 pairs, fold residual identity into w1
        for (int i = tid; i < 1024; i += blockDim.x) {
            int c = i >> 5, o = i & 31;
            float a = fusion_w[o * 64 + c] + ((o == c) ? 1.f : 0.f);
            float bw = fusion_w[o * 64 + 32 + c];
            ulonglong2 p;
            p.x = pack2(a);
            p.y = pack2(bw);
            g_wd[i] = p;
        }
        if (tid < 32) g_bd[tid] = pack2(fusion_b[tid]);
    }
}

// ---------------- main fused kernel ----------------
// block: (b, 16 t, 64 v) = 512 threads, one v-pair each, 32 f32x2 accumulators.
// Weights in __constant__ (uniform path, off the L1 crossbar).
// Double-buffered t-slab: 3 barriers per channel, store/prefetch overlaps FMA.
__global__ void __launch_bounds__(512, 1)
main_kernel(const float* __restrict__ x,
            float* __restrict__ out) {
    __shared__ U64 s_xs[2][64][32];   // double-buffered slab -> in-place prefix, 32KB
    __shared__ U64 s_seg[8][32];      // per-segment totals

    const int tid = threadIdx.x;
    const int b = blockIdx.z;
    const int t0 = blockIdx.y * 16;
    const int v0 = blockIdx.x * 64;

    const int col = tid & 31;      // v-pair
    const int tIdx = tid >> 5;     // 0..15
    const int L = 24 + tIdx;
    const U64 neg1 = pack2(-1.f);
    const size_t CH = (size_t)288 * 512;

    // epilogue operand prefetch (latency hidden behind the whole c-loop)
    const int t = t0 + tIdx;
    U64 cvu = *(const U64*)(g_cv + ((size_t)b * 288 + t) * 512 + v0 + col * 2);
    U64 imp2 = pack2(g_imp[b * 288 + t]);

    U64 acc[32];
    #pragma unroll
    for (int o = 0; o < 32; o++) acc[o] = c_bd[o];

    U64 cw[5];
    #pragma unroll
    for (int i = 0; i < 5; i++) cw[i] = pack2(g_cw[b][i]);

    // prefetch state: thread loads slab rows {tIdx, +16, +32, +48}
    const float* pc = x + (size_t)b * 32 * CH + v0 + col * 2;
    int roffB[4];
    bool vld[4];
    U64 pre[4];
    #pragma unroll
    for (int k = 0; k < 4; k++) {
        int gt = t0 - 24 + tIdx + 16 * k;
        vld[k] = (gt >= 0) && (gt < 288);
        roffB[k] = (vld[k] ? gt : 0) * 512;
        pre[k] = vld[k] ? *(const U64*)(pc + roffB[k]) : 0ull;
    }

    for (int c = 0; c < 32; c++) {
        U64 (*xs)[32] = s_xs[c & 1];
        // store slab (races only with same-buffer readers from c-2: separated by syncs)
        #pragma unroll
        for (int k = 0; k < 4; k++) xs[tIdx + 16 * k][col] = pre[k];
        // prefetch next channel (overlaps scan + fma of this channel)
        if (c < 31) {
            pc += CH;
            #pragma unroll
            for (int k = 0; k < 4; k++)
                pre[k] = vld[k] ? *(const U64*)(pc + roffB[k]) : 0ull;
        }
        __syncthreads();
        // segmented in-place exclusive prefix over t (8 segments of 8)
        if (tid < 256) {
            int seg = tid >> 5, cl = tid & 31, base = seg * 8;
            U64 run = 0ull;
            #pragma unroll
            for (int i = 0; i < 8; i++) {
                U64 tmp = xs[base + i][cl];
                xs[base + i][cl] = run;
                run = add2(run, tmp);
            }
            s_seg[seg][cl] = run;
        }
        __syncthreads();
        if (tid < 256) {
            int seg = tid >> 5, cl = tid & 31;
            if (seg >= 1) {
                U64 off = s_seg[0][cl];
                for (int s = 1; s < seg; s++) off = add2(off, s_seg[s][cl]);
                int base = seg * 8;
                #pragma unroll
                for (int i = 0; i < 8; i++)
                    xs[base + i][cl] = add2(xs[base + i][cl], off);
            }
        }
        __syncthreads();

        // x value and the 5 nested avg-pool window sums from the prefix
        U64 x2 = fma2(neg1, xs[L][col],      xs[L + 1][col]);
        U64 d0 = fma2(neg1, xs[L - 1][col],  xs[L + 2][col]);
        U64 d1 = fma2(neg1, xs[L - 3][col],  xs[L + 3][col]);
        U64 d2 = fma2(neg1, xs[L - 6][col],  xs[L + 6][col]);
        U64 d3 = fma2(neg1, xs[L - 12][col], xs[L + 12][col]);
        U64 d4 = fma2(neg1, xs[L - 24][col], xs[L + 24][col]);
        U64 cb = mul2(cw[0], d0);
        cb = fma2(cw[1], d1, cb);
        cb = fma2(cw[2], d2, cb);
        cb = fma2(cw[3], d3, cb);
        cb = fma2(cw[4], d4, cb);

        const ulonglong2* wrow = c_wd + c * 32;   // constant bank, uniform address
        #pragma unroll
        for (int o = 0; o < 32; o++) {
            ulonglong2 w = wrow[o];
            acc[o] = fma2(w.x, x2, acc[o]);
            acc[o] = fma2(w.y, cb, acc[o]);
        }
    }

    // epilogue: out = fused * (1 + cv) + impact   (residual+bias already in acc)
    U64 m2 = add2(pack2(1.f), cvu);
    float* po = out + ((size_t)b * 32 * CH) + (size_t)t * 512 + v0 + col * 2;
    #pragma unroll
    for (int o = 0; o < 32; o++) {
        *(U64*)(po + (size_t)o * CH) = fma2(acc[o], m2, imp2);
    }
}

// ---------------- launch ----------------
extern "C" void kernel_launch(void* const* d_in, const int* in_sizes, int n_in,
                              void* d_out, int out_size) {
    const float* flow   = (const float*)d_in[0];
    const float* events = (const float*)d_in[1];
    const float* x      = (const float*)d_in[2];
    const float* ef     = (const float*)d_in[3];
    const float* w1     = (const float*)d_in[4];
    const float* b1     = (const float*)d_in[5];
    const float* w2     = (const float*)d_in[6];
    const float* b2     = (const float*)d_in[7];
    const float* fw     = (const float*)d_in[8];
    const float* fb     = (const float*)d_in[9];
    float* out = (float*)d_out;

    prep_all<<<54, 512>>>(flow, events, ef, w1, b1, w2, b2, fw, fb);

    // stage packed weights/bias into the constant bank (async D2D, capturable)
    void* src_w = nullptr; void* src_b = nullptr;
    cudaGetSymbolAddress(&src_w, g_wd);
    cudaGetSymbolAddress(&src_b, g_bd);
    cudaMemcpyToSymbolAsync(c_wd, src_w, 1024 * sizeof(ulonglong2), 0,
                            cudaMemcpyDeviceToDevice);
    cudaMemcpyToSymbolAsync(c_bd, src_b, 32 * sizeof(U64), 0,
                            cudaMemcpyDeviceToDevice);

    dim3 grid(8, 18, 4);  // (V/64, T/16, B)
    main_kernel<<<grid, 512>>>(x, out);
}

// round 6
// speedup vs baseline: 2.6031x; 1.1263x over previous
#include <cuda_runtime.h>
#include <math.h>

typedef unsigned long long U64;

// ---------------- device scratch (static, no runtime allocs) ----------------
__device__ float g_cv[4 * 288 * 512];            // (B,T,V) rolling CV
__device__ float g_imp[4 * 288];                 // (B,T) summed event impact
__device__ float g_cb[4 * 32 * 288 * 512];       // (B,C,T,V) pooled combination
struct WPack {
    ulonglong2 wd[1024];   // [c][o] = {dup(w1+I), dup(w2)}
    U64 bd[32];            // dup bias
};
__device__ WPack g_wp;
__constant__ WPack c_wp;

// ---------------- packed f32x2 helpers (sm_103a) ----------------
static __device__ __forceinline__ U64 pack2(float x) {
    unsigned int u = __float_as_uint(x);
    U64 r;
    asm("mov.b64 %0, {%1, %2};" : "=l"(r) : "r"(u), "r"(u));
    return r;
}
static __device__ __forceinline__ U64 fma2(U64 a, U64 b, U64 c) {
    U64 d;
    asm("fma.rn.f32x2 %0, %1, %2, %3;" : "=l"(d) : "l"(a), "l"(b), "l"(c));
    return d;
}
static __device__ __forceinline__ U64 add2(U64 a, U64 b) {
    U64 d;
    asm("add.rn.f32x2 %0, %1, %2;" : "=l"(d) : "l"(a), "l"(b));
    return d;
}
static __device__ __forceinline__ U64 mul2(U64 a, U64 b) {
    U64 d;
    asm("mul.rn.f32x2 %0, %1, %2;" : "=l"(d) : "l"(a), "l"(b));
    return d;
}

// ---------------- prep: cv (0..47) + impact (48..51) + weight packing (52) ----------------
__global__ void prep_all(const float* __restrict__ flow,
                         const float* __restrict__ events,
                         const float* __restrict__ fusion_w,
                         const float* __restrict__ fusion_b) {
    const int blk = blockIdx.x;
    const int tid = threadIdx.x;

    if (blk < 48) {
        const int b = blk / 12;
        const int c0 = (blk % 12) * 24;
        const int v = tid;
        const float* f = flow + (size_t)b * 288 * 512 + v;
        int tstart = c0 - 59; if (tstart < 0) tstart = 0;
        float s = 0.f, s2 = 0.f;
        for (int t = tstart; t < c0 + 24; t++) {
            float a = f[(size_t)t * 512];
            s += a; s2 += a * a;
            int to = t - 60;
            if (to >= tstart) {
                float o = f[(size_t)to * 512];
                s -= o; s2 -= o * o;
            }
            if (t >= c0) {
                float cv = 0.f;
                if (t >= 59) {
                    float mean = s * (1.f / 60.f);
                    float var = (s2 - 60.f * mean * mean) * (1.f / 59.f);
                    float sd = sqrtf(fmaxf(var, 0.f));
                    cv = sd / (mean + 1e-6f);
                }
                g_cv[((size_t)b * 288 + t) * 512 + v] = cv;
            }
        }
    } else if (blk < 52) {
        const int b = blk - 48;
        const int t = tid;
        if (t < 288) {
            const float dec[3] = {300.f, 600.f, 180.f};
            const float al[3]  = {0.3f, 0.5f, 0.2f};
            float tot = 0.f;
            #pragma unroll
            for (int e = 0; e < 3; e++) {
                float r = expf(-1.f / dec[e]);
                float w = al[e], a = 0.f;
                for (int s = t; s < 288; s++) {
                    a = fmaf(events[((size_t)b * 288 + s) * 3 + e], w, a);
                    w *= r;
                }
                tot += a;
            }
            g_imp[b * 288 + t] = tot;
        }
    } else {
        for (int i = tid; i < 1024; i += blockDim.x) {
            int c = i >> 5, o = i & 31;
            float a = fusion_w[o * 64 + c] + ((o == c) ? 1.f : 0.f);
            float bw = fusion_w[o * 64 + 32 + c];
            ulonglong2 p;
            p.x = pack2(a);
            p.y = pack2(bw);
            g_wp.wd[i] = p;
        }
        if (tid < 32) g_wp.bd[tid] = pack2(fusion_b[tid]);
    }
}

// ---------------- kernel A: full-T prefix scan + pooled combination ----------------
// block = (b, c, 32-v tile), 256 threads. One scan per block, 4 barriers total.
__global__ void __launch_bounds__(256)
scan_kernel(const float* __restrict__ x,
            const float* __restrict__ ef,
            const float* __restrict__ w1,
            const float* __restrict__ b1,
            const float* __restrict__ w2,
            const float* __restrict__ b2) {
    __shared__ U64 s_ps[289][16];   // inclusive prefix (row i = sum x[0..i-1]), 37KB
    __shared__ float s_h[32];
    __shared__ float s_lg[5];

    const int tid = threadIdx.x;
    const int v0 = blockIdx.x * 32;     // 16 v-pairs
    const int c  = blockIdx.y;
    const int b  = blockIdx.z;

    // load the whole T column for this (b,c,v-tile)
    const float* xb = x + ((size_t)(b * 32 + c) * 288) * 512 + v0;
    #pragma unroll
    for (int k = 0; k < 18; k++) {
        int idx = tid + k * 256;
        int r = idx >> 4, cl = idx & 15;
        s_ps[1 + r][cl] = *(const U64*)(xb + (size_t)r * 512 + cl * 2);
    }
    if (tid < 16) s_ps[0][tid] = 0ull;

    // gate MLP hidden layer (inline, removes prep dependency)
    if (tid < 32) {
        float a = b1[tid];
        #pragma unroll
        for (int i = 0; i < 8; i++) a += ef[b * 8 + i] * w1[i * 32 + tid];
        s_h[tid] = fmaxf(a, 0.f);
    }
    __syncthreads();

    // logits -> sigmoid (5 threads), in parallel with phase-1 scan
    if (tid < 5) {
        float a = b2[tid];
        #pragma unroll
        for (int i = 0; i < 32; i++) a += s_h[i] * w2[i * 5 + tid];
        s_lg[tid] = 1.f / (1.f + expf(-a));
    }

    // phase 1: in-segment inclusive scan (16 segments x 18 rows, all threads busy)
    const int seg = tid >> 4, cl = tid & 15;
    {
        int r0 = 1 + seg * 18;
        U64 run = 0ull;
        #pragma unroll
        for (int i = 0; i < 18; i++) {
            run = add2(run, s_ps[r0 + i][cl]);
            s_ps[r0 + i][cl] = run;
        }
    }
    __syncthreads();

    // phase 2a: gather segment-total prefix into registers (no writes yet)
    U64 off = 0ull;
    if (seg > 0) {
        off = s_ps[18][cl];
        for (int s = 2; s <= seg; s++) off = add2(off, s_ps[18 * s][cl]);
    }
    __syncthreads();

    // phase 2b: apply offsets; every thread also finalizes its gate weights
    if (seg > 0) {
        int r0 = 1 + seg * 18;
        #pragma unroll
        for (int i = 0; i < 18; i++)
            s_ps[r0 + i][cl] = add2(s_ps[r0 + i][cl], off);
    }
    float lg0 = s_lg[0], lg1 = s_lg[1], lg2 = s_lg[2], lg3 = s_lg[3], lg4 = s_lg[4];
    float mx = fmaxf(fmaxf(fmaxf(lg0, lg1), fmaxf(lg2, lg3)), lg4);
    float e0 = expf(lg0 - mx), e1 = expf(lg1 - mx), e2 = expf(lg2 - mx),
          e3 = expf(lg3 - mx), e4 = expf(lg4 - mx);
    float inv = 1.f / (e0 + e1 + e2 + e3 + e4);
    U64 cw[5];
    cw[0] = pack2(e0 * inv * (1.f / 3.f));
    cw[1] = pack2(e1 * inv * (1.f / 6.f));
    cw[2] = pack2(e2 * inv * (1.f / 12.f));
    cw[3] = pack2(e3 * inv * (1.f / 24.f));
    cw[4] = pack2(e4 * inv * (1.f / 48.f));
    __syncthreads();

    // compute cb for all (t, v-pair) points and store
    const U64 neg1 = pack2(-1.f);
    float* cbase = g_cb + ((size_t)(b * 32 + c) * 288) * 512 + v0;
    #pragma unroll
    for (int k = 0; k < 18; k++) {
        int idx = tid + k * 256;
        int t = idx >> 4, cl2 = idx & 15;
        // clamped prefix taps: window [a, a+K) with a = t - K/2, clamp to [0,288]
        int a3  = max(t - 1, 0),  b3  = min(t + 2, 288);
        int a6  = max(t - 3, 0),  b6  = min(t + 3, 288);
        int a12 = max(t - 6, 0),  b12 = min(t + 6, 288);
        int a24 = max(t - 12, 0), b24 = min(t + 12, 288);
        int a48 = max(t - 24, 0), b48 = min(t + 24, 288);
        U64 d0 = fma2(neg1, s_ps[a3][cl2],  s_ps[b3][cl2]);
        U64 d1 = fma2(neg1, s_ps[a6][cl2],  s_ps[b6][cl2]);
        U64 d2 = fma2(neg1, s_ps[a12][cl2], s_ps[b12][cl2]);
        U64 d3 = fma2(neg1, s_ps[a24][cl2], s_ps[b24][cl2]);
        U64 d4 = fma2(neg1, s_ps[a48][cl2], s_ps[b48][cl2]);
        U64 cb = mul2(cw[0], d0);
        cb = fma2(cw[1], d1, cb);
        cb = fma2(cw[2], d2, cb);
        cb = fma2(cw[3], d3, cb);
        cb = fma2(cw[4], d4, cb);
        *(U64*)(cbase + (size_t)t * 512 + cl2 * 2) = cb;
    }
}

// ---------------- kernel B: pointwise 64->32 projection, zero barriers ----------------
// block = one (b,t) row, thread = one v-pair. Weights via const bank.
__global__ void __launch_bounds__(256, 2)
proj_kernel(const float* __restrict__ x, float* __restrict__ out) {
    const int vp = threadIdx.x;
    const int bt = blockIdx.x;
    const int b = bt / 288, t = bt - b * 288;
    const size_t CH = (size_t)288 * 512;
    const size_t base = ((size_t)b * 32 * 288 + t) * 512 + 2 * vp;
    const float* px  = x + base;
    const float* pcb = g_cb + base;

    // epilogue operands prefetched up front
    U64 cvu  = *(const U64*)(g_cv + ((size_t)b * 288 + t) * 512 + 2 * vp);
    U64 imp2 = pack2(g_imp[b * 288 + t]);

    U64 acc[32];
    #pragma unroll
    for (int o = 0; o < 32; o++) acc[o] = c_wp.bd[o];

    // 2-stage software pipeline over channels
    U64 xv = *(const U64*)(px);
    U64 cb = *(const U64*)(pcb);
    #pragma unroll 4
    for (int c = 0; c < 32; c++) {
        U64 xv_n = 0ull, cb_n = 0ull;
        if (c < 31) {
            xv_n = *(const U64*)(px  + (size_t)(c + 1) * CH);
            cb_n = *(const U64*)(pcb + (size_t)(c + 1) * CH);
        }
        const ulonglong2* w = c_wp.wd + c * 32;
        #pragma unroll
        for (int o = 0; o < 32; o++) {
            acc[o] = fma2(w[o].x, xv, acc[o]);
            acc[o] = fma2(w[o].y, cb, acc[o]);
        }
        xv = xv_n; cb = cb_n;
    }

    U64 m2 = add2(pack2(1.f), cvu);
    float* po = out + base;
    #pragma unroll
    for (int o = 0; o < 32; o++)
        *(U64*)(po + (size_t)o * CH) = fma2(acc[o], m2, imp2);
}

// ---------------- launch ----------------
extern "C" void kernel_launch(void* const* d_in, const int* in_sizes, int n_in,
                              void* d_out, int out_size) {
    const float* flow   = (const float*)d_in[0];
    const float* events = (const float*)d_in[1];
    const float* x      = (const float*)d_in[2];
    const float* ef     = (const float*)d_in[3];
    const float* w1     = (const float*)d_in[4];
    const float* b1     = (const float*)d_in[5];
    const float* w2     = (const float*)d_in[6];
    const float* b2     = (const float*)d_in[7];
    const float* fw     = (const float*)d_in[8];
    const float* fb     = (const float*)d_in[9];
    float* out = (float*)d_out;

    prep_all<<<53, 512>>>(flow, events, fw, fb);

    dim3 gA(16, 32, 4);  // (V/32, C, B)
    scan_kernel<<<gA, 256>>>(x, ef, w1, b1, w2, b2);

    // single const-bank staging copy (D2D, graph-capturable)
    void* src = nullptr;
    cudaGetSymbolAddress(&src, g_wp);
    cudaMemcpyToSymbolAsync(c_wp, src, sizeof(WPack), 0, cudaMemcpyDeviceToDevice);

    proj_kernel<<<4 * 288, 256>>>(x, out);
}